// round 16
// baseline (speedup 1.0000x reference)
#include <cuda_runtime.h>
#include <cuda_bf16.h>
#include <cstdint>
#include <cstring>

#define NN 100000
#define EE_MAX 3200000
#define CSR_MAX (EE_MAX + NN)
#define SCAN_BLK 1024
#define NBLK ((NN + SCAN_BLK - 1) / SCAN_BLK)   // 98

// ---------------- device scratch (static, allocation-free) ----------------
__device__ __nv_bfloat16 g_h1b[NN * 64];     // layer1 features bf16
__device__ float g_as1[NN * 8];
__device__ float g_ad1[NN * 8];
__device__ float g_out1[NN * 64];            // layer1 output fp32
__device__ __nv_bfloat16 g_h2b[NN * 8];      // layer2 features bf16 [N,7]+ones
__device__ float g_as2[NN];
__device__ float g_ad2[NN];
__device__ float g_W1t[64 * 512];            // W1 transposed [N=64][K=512]

__device__ int g_cnt[NN];                    // degree + 1 (self loop)
__device__ int g_start[NN];
__device__ int g_bsum[NBLK];
__device__ int g_rank[EE_MAX];               // edge rank within its dst (>=1)
__device__ int g_csr[CSR_MAX];               // [self | in-edges] per dst

__device__ __forceinline__ float lrexp(float x) {
    x = x > 0.0f ? x : 0.2f * x;
    return __expf(x);
}

__device__ __forceinline__ uint32_t bf2_bits(__nv_bfloat162 v) {
    uint32_t u;
    memcpy(&u, &v, 4);
    return u;
}

__device__ __forceinline__ uint32_t smem_u32(const void* p) {
    uint32_t a;
    asm("{ .reg .u64 t; cvta.to.shared.u64 t, %1; cvt.u32.u64 %0, t; }" : "=r"(a) : "l"(p));
    return a;
}
__device__ __forceinline__ void cpa16(uint32_t saddr, const void* g, int src_sz) {
    asm volatile("cp.async.cg.shared.global [%0], [%1], 16, %2;"
                 :: "r"(saddr), "l"(g), "r"(src_sz) : "memory");
}
#define CPA_COMMIT() asm volatile("cp.async.commit_group;" ::: "memory")
#define CPA_WAIT(n)  asm volatile("cp.async.wait_group %0;" :: "n"(n) : "memory")

__device__ __forceinline__ void mma_tf32(float& c0, float& c1, float& c2, float& c3,
                                         uint32_t a0, uint32_t a1, uint32_t a2, uint32_t a3,
                                         uint32_t b0, uint32_t b1) {
    asm volatile(
        "mma.sync.aligned.m16n8k8.row.col.f32.tf32.tf32.f32 "
        "{%0,%1,%2,%3}, {%4,%5,%6,%7}, {%8,%9}, {%0,%1,%2,%3};"
        : "+f"(c0), "+f"(c1), "+f"(c2), "+f"(c3)
        : "r"(a0), "r"(a1), "r"(a2), "r"(a3), "r"(b0), "r"(b1));
}

// ---------------- CSR chain kernels ----------------
__global__ void prepcnt_kernel() {
    int i = blockIdx.x * blockDim.x + threadIdx.x;
    if (i < NN) g_cnt[i] = 1;          // slot 0 reserved for self loop
}

__global__ void transposeW1_kernel(const float* __restrict__ W1) {
    int i = blockIdx.x * blockDim.x + threadIdx.x;
    if (i < 512 * 64) {
        int k = i >> 6, n = i & 63;
        g_W1t[n * 512 + k] = W1[i];
    }
}

__global__ void hist_kernel(const int* __restrict__ dst, int E) {
    int e = blockIdx.x * blockDim.x + threadIdx.x;
    if (e < E) g_rank[e] = atomicAdd(&g_cnt[dst[e]], 1);
}

__global__ __launch_bounds__(256) void scan1_kernel() {
    __shared__ int warp_tot[8];
    int b = blockIdx.x, t = threadIdx.x;
    int base = b * SCAN_BLK + t * 4;
    int v[4];
#pragma unroll
    for (int k = 0; k < 4; k++) v[k] = (base + k < NN) ? g_cnt[base + k] : 0;
    int tsum = v[0] + v[1] + v[2] + v[3];
    int lane = t & 31, wid = t >> 5;
    int inc = tsum;
#pragma unroll
    for (int off = 1; off < 32; off <<= 1) {
        int n = __shfl_up_sync(0xffffffffu, inc, off);
        if (lane >= off) inc += n;
    }
    if (lane == 31) warp_tot[wid] = inc;
    __syncthreads();
    if (wid == 0) {
        int w = (lane < 8) ? warp_tot[lane] : 0;
#pragma unroll
        for (int off = 1; off < 8; off <<= 1) {
            int n = __shfl_up_sync(0xffffffffu, w, off);
            if (lane >= off) w += n;
        }
        if (lane < 8) warp_tot[lane] = w;
    }
    __syncthreads();
    int excl = inc - tsum + (wid > 0 ? warp_tot[wid - 1] : 0);
#pragma unroll
    for (int k = 0; k < 4; k++) {
        if (base + k < NN) g_start[base + k] = excl;
        excl += v[k];
    }
    if (t == 255) g_bsum[b] = excl;
}

// scan3: parallel cross-block prefix + write self entry into CSR slot 0
__global__ __launch_bounds__(256) void scan3_kernel() {
    __shared__ int sb[128];
    int t = threadIdx.x;
    if (t < 128) sb[t] = (t < NBLK) ? g_bsum[t] : 0;
    __syncthreads();
#pragma unroll
    for (int off = 1; off < 128; off <<= 1) {
        int x = 0;
        if (t < 128 && t >= off) x = sb[t - off];
        __syncthreads();
        if (t < 128) sb[t] += x;
        __syncthreads();
    }
    int i = blockIdx.x * 256 + t;
    if (i < NN) {
        int seg = i >> 10;
        int pre = (seg > 0) ? sb[seg - 1] : 0;
        int s = g_start[i] + pre;
        g_start[i] = s;
        g_csr[s] = i;          // self-loop entry at slot 0
    }
}

__global__ void scatter_kernel(const int* __restrict__ src,
                               const int* __restrict__ dst, int E) {
    int e = blockIdx.x * blockDim.x + threadIdx.x;
    if (e < E)
        g_csr[g_start[dst[e]] + g_rank[e]] = src[e];
}

// ---------------- tf32 mma.sync GEMM1 + fused alpha epilogue ----------------
#define KC 32
#define ASTRIDE 36

__global__ __launch_bounds__(256) void sgemm1_mma_kernel(const float* __restrict__ A,
                                                         const float* __restrict__ a_src,
                                                         const float* __restrict__ a_dst) {
    __shared__ uint32_t As[2][128 * ASTRIDE];
    __shared__ uint32_t Bs[2][64 * ASTRIDE];
    __shared__ float sattn[128];
    int t = threadIdx.x;
    int lane = t & 31, wid = t >> 5;
    int g = lane >> 2, tg = lane & 3;
    int warpM = (wid & 3) * 32;
    int warpN = (wid >> 2) * 32;
    int row0 = blockIdx.x * 128;

    if (t < 64) sattn[t] = a_src[t];
    else if (t < 128) sattn[t] = a_dst[t - 64];

    float c[2][4][4];
#pragma unroll
    for (int mi = 0; mi < 2; mi++)
#pragma unroll
        for (int ni = 0; ni < 4; ni++)
#pragma unroll
            for (int q = 0; q < 4; q++) c[mi][ni][q] = 0.f;

#pragma unroll
    for (int i = 0; i < 4; i++) {
        int idx = t + i * 256;
        int r = idx >> 3, q = idx & 7;
        int row = row0 + r;
        int rc = row < NN ? row : NN - 1;
        int sz = row < NN ? 16 : 0;
        cpa16(smem_u32(&As[0][r * ASTRIDE + q * 4]),
              A + (size_t)rc * 512 + q * 4, sz);
    }
#pragma unroll
    for (int i = 0; i < 2; i++) {
        int idx = t + i * 256;
        int r = idx >> 3, q = idx & 7;
        cpa16(smem_u32(&Bs[0][r * ASTRIDE + q * 4]),
              g_W1t + (size_t)r * 512 + q * 4, 16);
    }
    CPA_COMMIT();

    for (int cidx = 0; cidx < 16; cidx++) {
        int b = cidx & 1;
        if (cidx < 15) {
            int kk = (cidx + 1) * KC;
            int bn = b ^ 1;
#pragma unroll
            for (int i = 0; i < 4; i++) {
                int idx = t + i * 256;
                int r = idx >> 3, q = idx & 7;
                int row = row0 + r;
                int rc = row < NN ? row : NN - 1;
                int sz = row < NN ? 16 : 0;
                cpa16(smem_u32(&As[bn][r * ASTRIDE + q * 4]),
                      A + (size_t)rc * 512 + kk + q * 4, sz);
            }
#pragma unroll
            for (int i = 0; i < 2; i++) {
                int idx = t + i * 256;
                int r = idx >> 3, q = idx & 7;
                cpa16(smem_u32(&Bs[bn][r * ASTRIDE + q * 4]),
                      g_W1t + (size_t)r * 512 + kk + q * 4, 16);
            }
            CPA_COMMIT();
            CPA_WAIT(1);
        } else {
            CPA_WAIT(0);
        }
        __syncthreads();
#pragma unroll
        for (int k8 = 0; k8 < 4; k8++) {
            int kb = k8 * 8;
            uint32_t a[2][4], bb[4][2];
#pragma unroll
            for (int mi = 0; mi < 2; mi++) {
                int m = warpM + mi * 16;
                a[mi][0] = As[b][(m + g) * ASTRIDE + kb + tg];
                a[mi][1] = As[b][(m + g + 8) * ASTRIDE + kb + tg];
                a[mi][2] = As[b][(m + g) * ASTRIDE + kb + tg + 4];
                a[mi][3] = As[b][(m + g + 8) * ASTRIDE + kb + tg + 4];
            }
#pragma unroll
            for (int ni = 0; ni < 4; ni++) {
                int n = warpN + ni * 8;
                bb[ni][0] = Bs[b][(n + g) * ASTRIDE + kb + tg];
                bb[ni][1] = Bs[b][(n + g) * ASTRIDE + kb + tg + 4];
            }
#pragma unroll
            for (int mi = 0; mi < 2; mi++)
#pragma unroll
                for (int ni = 0; ni < 4; ni++)
                    mma_tf32(c[mi][ni][0], c[mi][ni][1], c[mi][ni][2], c[mi][ni][3],
                             a[mi][0], a[mi][1], a[mi][2], a[mi][3],
                             bb[ni][0], bb[ni][1]);
        }
        __syncthreads();
    }

    // ---- fused epilogue: stage bf16 tile in smem (reuse As[0]) ----
    uint32_t* Hs = &As[0][0];
#pragma unroll
    for (int mi = 0; mi < 2; mi++) {
        int r0 = warpM + mi * 16 + g;
        int r1 = r0 + 8;
#pragma unroll
        for (int ni = 0; ni < 4; ni++) {
            int cp = (warpN + ni * 8 + tg * 2) >> 1;   // col-pair index 0..31
            Hs[r0 * ASTRIDE + cp] =
                bf2_bits(__floats2bfloat162_rn(c[mi][ni][0], c[mi][ni][1]));
            Hs[r1 * ASTRIDE + cp] =
                bf2_bits(__floats2bfloat162_rn(c[mi][ni][2], c[mi][ni][3]));
        }
    }
    __syncthreads();
    // write h1b: thread t -> row t>>1, half t&1 (32B each)
    {
        int r = t >> 1, hf = t & 1;
        int row = row0 + r;
        if (row < NN) {
            const uint32_t* sp = &Hs[r * ASTRIDE + hf * 16];
            uint4* dp = reinterpret_cast<uint4*>(g_h1b + (size_t)row * 64 + hf * 32);
            dp[0] = *reinterpret_cast<const uint4*>(sp);
            dp[1] = *reinterpret_cast<const uint4*>(sp + 4);
            dp[2] = *reinterpret_cast<const uint4*>(sp + 8);
            dp[3] = *reinterpret_cast<const uint4*>(sp + 12);
        }
    }
    // alpha logits: threads 0-127 -> a_src dot; 128-255 -> a_dst dot
    {
        int r = t & 127;
        int row = row0 + r;
        if (row < NN) {
            const __nv_bfloat162* hp = reinterpret_cast<const __nv_bfloat162*>(&Hs[r * ASTRIDE]);
            const float* coef = sattn + (t < 128 ? 0 : 64);
            float res[8];
#pragma unroll
            for (int h = 0; h < 8; h++) {
                float s = 0.f;
#pragma unroll
                for (int q = 0; q < 4; q++) {
                    float2 f = __bfloat1622float2(hp[h * 4 + q]);
                    s += f.x * coef[h * 8 + 2 * q] + f.y * coef[h * 8 + 2 * q + 1];
                }
                res[h] = s;
            }
            float* dst = (t < 128 ? g_as1 : g_ad1) + (size_t)row * 8;
            *reinterpret_cast<float4*>(dst) = make_float4(res[0], res[1], res[2], res[3]);
            *reinterpret_cast<float4*>(dst + 4) = make_float4(res[4], res[5], res[6], res[7]);
        }
    }
}

// ---------------- layer-1 gather: 8 lanes per dst node, lane = head --------
__global__ __launch_bounds__(256) void gather1_kernel(const float* __restrict__ b1) {
    int gid = blockIdx.x * blockDim.x + threadIdx.x;
    int n = gid >> 3;
    if (n >= NN) return;
    int h = gid & 7;
    float ad_h = g_ad1[n * 8 + h];
    int st = g_start[n];
    int deg = g_cnt[n];                 // includes self
    float acc[8];
#pragma unroll
    for (int j = 0; j < 8; j++) acc[j] = 0.f;
    float den = 0.f;
    int i = 0;
    for (; i + 2 <= deg; i += 2) {
        int s0 = g_csr[st + i];
        int s1 = g_csr[st + i + 1];
        float w0 = lrexp(g_as1[s0 * 8 + h] + ad_h);
        float w1 = lrexp(g_as1[s1 * 8 + h] + ad_h);
        uint4 r0 = *reinterpret_cast<const uint4*>(g_h1b + (size_t)s0 * 64 + h * 8);
        uint4 r1 = *reinterpret_cast<const uint4*>(g_h1b + (size_t)s1 * 64 + h * 8);
        const __nv_bfloat162* f0 = reinterpret_cast<const __nv_bfloat162*>(&r0);
        const __nv_bfloat162* f1 = reinterpret_cast<const __nv_bfloat162*>(&r1);
#pragma unroll
        for (int q = 0; q < 4; q++) {
            float2 a0 = __bfloat1622float2(f0[q]);
            float2 a1 = __bfloat1622float2(f1[q]);
            acc[2 * q] += w0 * a0.x + w1 * a1.x;
            acc[2 * q + 1] += w0 * a0.y + w1 * a1.y;
        }
        den += w0 + w1;
    }
    if (i < deg) {
        int s0 = g_csr[st + i];
        float w0 = lrexp(g_as1[s0 * 8 + h] + ad_h);
        uint4 r0 = *reinterpret_cast<const uint4*>(g_h1b + (size_t)s0 * 64 + h * 8);
        const __nv_bfloat162* f0 = reinterpret_cast<const __nv_bfloat162*>(&r0);
#pragma unroll
        for (int q = 0; q < 4; q++) {
            float2 a0 = __bfloat1622float2(f0[q]);
            acc[2 * q] += w0 * a0.x;
            acc[2 * q + 1] += w0 * a0.y;
        }
        den += w0;
    }
    float inv = 1.0f / (den + 1e-16f);
    float4 bv0 = *reinterpret_cast<const float4*>(b1 + h * 8);
    float4 bv1 = *reinterpret_cast<const float4*>(b1 + h * 8 + 4);
    float* op = g_out1 + (size_t)n * 64 + h * 8;
    *reinterpret_cast<float4*>(op) =
        make_float4(acc[0] * inv + bv0.x, acc[1] * inv + bv0.y,
                    acc[2] * inv + bv0.z, acc[3] * inv + bv0.w);
    *reinterpret_cast<float4*>(op + 4) =
        make_float4(acc[4] * inv + bv1.x, acc[5] * inv + bv1.y,
                    acc[6] * inv + bv1.z, acc[7] * inv + bv1.w);
}

// ---------------- layer-2 transform (bf16 h2 out) ----------------
__global__ __launch_bounds__(128) void gemm2_kernel(const float* __restrict__ W2,
                                                    const float* __restrict__ a_src,
                                                    const float* __restrict__ a_dst) {
    __shared__ float sW[448];
    __shared__ float sa[7], sd[7];
    int t = threadIdx.x;
    for (int j = t; j < 448; j += blockDim.x) sW[j] = W2[j];
    if (t < 7) { sa[t] = a_src[t]; sd[t] = a_dst[t]; }
    __syncthreads();
    int n = blockIdx.x * blockDim.x + t;
    if (n >= NN) return;
    float v[64];
    const float4* row = (const float4*)g_out1 + (size_t)n * 16;
#pragma unroll
    for (int q = 0; q < 16; q++) {
        float4 x = row[q];
        v[4 * q] = x.x; v[4 * q + 1] = x.y; v[4 * q + 2] = x.z; v[4 * q + 3] = x.w;
    }
    float h[7] = {0.f, 0.f, 0.f, 0.f, 0.f, 0.f, 0.f};
#pragma unroll 8
    for (int k = 0; k < 64; k++) {
        float vk = v[k];
#pragma unroll
        for (int c = 0; c < 7; c++) h[c] += vk * sW[k * 7 + c];
    }
    float s = 0.f, d = 0.f;
#pragma unroll
    for (int c = 0; c < 7; c++) { s += h[c] * sa[c]; d += h[c] * sd[c]; }
    uint4 pk;
    pk.x = bf2_bits(__floats2bfloat162_rn(h[0], h[1]));
    pk.y = bf2_bits(__floats2bfloat162_rn(h[2], h[3]));
    pk.z = bf2_bits(__floats2bfloat162_rn(h[4], h[5]));
    pk.w = bf2_bits(__floats2bfloat162_rn(h[6], 1.0f));
    *reinterpret_cast<uint4*>(g_h2b + (size_t)n * 8) = pk;
    g_as2[n] = s;
    g_ad2[n] = d;
}

// ---------------- layer-2 gather (8 lanes/node, bf16 h2, log_softmax) ------
__global__ __launch_bounds__(256) void gather2_kernel(const float* __restrict__ b2,
                                                      float* __restrict__ out) {
    int gid = blockIdx.x * blockDim.x + threadIdx.x;
    int n = gid >> 3;
    if (n >= NN) return;
    int c = gid & 7;
    float ad = g_ad2[n];
    int st = g_start[n];
    int deg = g_cnt[n];                 // includes self
    float acc = 0.f;
    int i = 0;
    for (; i + 2 <= deg; i += 2) {
        int s0 = g_csr[st + i];
        int s1 = g_csr[st + i + 1];
        float w0 = lrexp(g_as2[s0] + ad);
        float w1 = lrexp(g_as2[s1] + ad);
        acc += w0 * __bfloat162float(g_h2b[(size_t)s0 * 8 + c]) +
               w1 * __bfloat162float(g_h2b[(size_t)s1 * 8 + c]);
    }
    if (i < deg) {
        int s0 = g_csr[st + i];
        float w0 = lrexp(g_as2[s0] + ad);
        acc += w0 * __bfloat162float(g_h2b[(size_t)s0 * 8 + c]);
    }
    float den = __shfl_sync(0xffffffffu, acc, (threadIdx.x & ~7) | 7);
    float inv = 1.0f / (den + 1e-16f);
    float o = (c < 7) ? (acc * inv + b2[c]) : -1e30f;
    float m = o;
#pragma unroll
    for (int off = 1; off < 8; off <<= 1)
        m = fmaxf(m, __shfl_xor_sync(0xffffffffu, m, off));
    float ex = (c < 7) ? __expf(o - m) : 0.f;
    float sum = ex;
#pragma unroll
    for (int off = 1; off < 8; off <<= 1)
        sum += __shfl_xor_sync(0xffffffffu, sum, off);
    float lse = m + logf(sum);
    if (c < 7) out[(size_t)n * 7 + c] = o - lse;
}

// ---------------- launcher (two concurrent chains, fork/join events) -------
extern "C" void kernel_launch(void* const* d_in, const int* in_sizes, int n_in,
                              void* d_out, int out_size) {
    const float* x    = (const float*)d_in[0];
    const int*   ei   = (const int*)d_in[1];
    const float* W1   = (const float*)d_in[2];
    const float* as1  = (const float*)d_in[3];
    const float* ad1  = (const float*)d_in[4];
    const float* b1   = (const float*)d_in[5];
    const float* W2   = (const float*)d_in[6];
    const float* as2  = (const float*)d_in[7];
    const float* ad2  = (const float*)d_in[8];
    const float* b2   = (const float*)d_in[9];
    float* out = (float*)d_out;
    int E = in_sizes[1] / 2;
    const int* src = ei;
    const int* dst = ei + E;

    // fork a second stream for the CSR chain (graph-capture-safe fork/join)
    cudaStream_t s2;
    cudaEvent_t evFork, evJoin;
    cudaStreamCreateWithFlags(&s2, cudaStreamNonBlocking);
    cudaEventCreateWithFlags(&evFork, cudaEventDisableTiming);
    cudaEventCreateWithFlags(&evJoin, cudaEventDisableTiming);

    cudaEventRecord(evFork, 0);
    cudaStreamWaitEvent(s2, evFork, 0);

    // CSR chain on s2
    prepcnt_kernel<<<(NN + 255) / 256, 256, 0, s2>>>();
    hist_kernel<<<(E + 255) / 256, 256, 0, s2>>>(dst, E);
    scan1_kernel<<<NBLK, 256, 0, s2>>>();
    scan3_kernel<<<(NN + 255) / 256, 256, 0, s2>>>();
    scatter_kernel<<<(E + 255) / 256, 256, 0, s2>>>(src, dst, E);
    cudaEventRecord(evJoin, s2);

    // GEMM chain on main stream (concurrent with CSR chain)
    transposeW1_kernel<<<(512 * 64 + 255) / 256, 256>>>(W1);
    sgemm1_mma_kernel<<<(NN + 127) / 128, 256>>>(x, as1, ad1);

    // join: gathers need both chains
    cudaStreamWaitEvent(0, evJoin, 0);
    gather1_kernel<<<(NN * 8 + 255) / 256, 256>>>(b1);
    gemm2_kernel<<<(NN + 127) / 128, 128>>>(W2, as2, ad2);
    gather2_kernel<<<(NN * 8 + 255) / 256, 256>>>(b2, out);
    // NOTE: streams/events intentionally not destroyed here — destroying a
    // stream participating in an active graph capture is invalid; the few
    // handles created per call (correctness + capture) are bounded.
}

// round 17
// speedup vs baseline: 1.0301x; 1.0301x over previous
#include <cuda_runtime.h>
#include <cuda_bf16.h>
#include <cstdint>
#include <cstring>

#define NN 100000
#define EE_MAX 3200000
#define CSR_MAX (EE_MAX + NN)
#define SCAN_BLK 1024
#define NBLK ((NN + SCAN_BLK - 1) / SCAN_BLK)   // 98

// ---------------- device scratch (static, allocation-free) ----------------
__device__ __nv_bfloat16 g_h1b[NN * 64];     // layer1 features bf16
__device__ float g_as1[NN * 8];
__device__ float g_ad1[NN * 8];
__device__ __nv_bfloat16 g_h2b[NN * 8];      // layer2 features bf16 [N,7]+ones
__device__ float g_as2[NN];
__device__ float g_ad2[NN];
__device__ float g_W1t[64 * 512];            // W1 transposed [N=64][K=512]

__device__ int g_cnt[NN];                    // degree + 1 (self loop)
__device__ int g_start[NN];
__device__ int g_bsum[NBLK];
__device__ int g_rank[EE_MAX];               // edge rank within its dst (>=1)
__device__ int g_csr[CSR_MAX];               // [self | in-edges] per dst

__device__ __forceinline__ float lrexp(float x) {
    x = x > 0.0f ? x : 0.2f * x;
    return __expf(x);
}

__device__ __forceinline__ uint32_t bf2_bits(__nv_bfloat162 v) {
    uint32_t u;
    memcpy(&u, &v, 4);
    return u;
}

__device__ __forceinline__ uint32_t smem_u32(const void* p) {
    uint32_t a;
    asm("{ .reg .u64 t; cvta.to.shared.u64 t, %1; cvt.u32.u64 %0, t; }" : "=r"(a) : "l"(p));
    return a;
}
__device__ __forceinline__ void cpa16(uint32_t saddr, const void* g, int src_sz) {
    asm volatile("cp.async.cg.shared.global [%0], [%1], 16, %2;"
                 :: "r"(saddr), "l"(g), "r"(src_sz) : "memory");
}
#define CPA_COMMIT() asm volatile("cp.async.commit_group;" ::: "memory")
#define CPA_WAIT(n)  asm volatile("cp.async.wait_group %0;" :: "n"(n) : "memory")

__device__ __forceinline__ void mma_tf32(float& c0, float& c1, float& c2, float& c3,
                                         uint32_t a0, uint32_t a1, uint32_t a2, uint32_t a3,
                                         uint32_t b0, uint32_t b1) {
    asm volatile(
        "mma.sync.aligned.m16n8k8.row.col.f32.tf32.tf32.f32 "
        "{%0,%1,%2,%3}, {%4,%5,%6,%7}, {%8,%9}, {%0,%1,%2,%3};"
        : "+f"(c0), "+f"(c1), "+f"(c2), "+f"(c3)
        : "r"(a0), "r"(a1), "r"(a2), "r"(a3), "r"(b0), "r"(b1));
}

// ---------------- prep: cnt=1 (self slot) + transpose W1 (fused) -----------
__global__ void prep_kernel(const float* __restrict__ W1) {
    int i = blockIdx.x * blockDim.x + threadIdx.x;
    if (i < NN) g_cnt[i] = 1;
    if (i < 512 * 64) {
        int k = i >> 6, n = i & 63;
        g_W1t[n * 512 + k] = W1[i];
    }
}

// ---------------- hist + rank (ranks start at 1; slot 0 = self) ------------
__global__ void hist_kernel(const int* __restrict__ dst, int E) {
    int e = blockIdx.x * blockDim.x + threadIdx.x;
    if (e < E) g_rank[e] = atomicAdd(&g_cnt[dst[e]], 1);
}

__global__ __launch_bounds__(256) void scan1_kernel() {
    __shared__ int warp_tot[8];
    int b = blockIdx.x, t = threadIdx.x;
    int base = b * SCAN_BLK + t * 4;
    int v[4];
#pragma unroll
    for (int k = 0; k < 4; k++) v[k] = (base + k < NN) ? g_cnt[base + k] : 0;
    int tsum = v[0] + v[1] + v[2] + v[3];
    int lane = t & 31, wid = t >> 5;
    int inc = tsum;
#pragma unroll
    for (int off = 1; off < 32; off <<= 1) {
        int n = __shfl_up_sync(0xffffffffu, inc, off);
        if (lane >= off) inc += n;
    }
    if (lane == 31) warp_tot[wid] = inc;
    __syncthreads();
    if (wid == 0) {
        int w = (lane < 8) ? warp_tot[lane] : 0;
#pragma unroll
        for (int off = 1; off < 8; off <<= 1) {
            int n = __shfl_up_sync(0xffffffffu, w, off);
            if (lane >= off) w += n;
        }
        if (lane < 8) warp_tot[lane] = w;
    }
    __syncthreads();
    int excl = inc - tsum + (wid > 0 ? warp_tot[wid - 1] : 0);
#pragma unroll
    for (int k = 0; k < 4; k++) {
        if (base + k < NN) g_start[base + k] = excl;
        excl += v[k];
    }
    if (t == 255) g_bsum[b] = excl;
}

// scan3: parallel cross-block prefix + write self entry into CSR slot 0
__global__ __launch_bounds__(256) void scan3_kernel() {
    __shared__ int sb[128];
    int t = threadIdx.x;
    if (t < 128) sb[t] = (t < NBLK) ? g_bsum[t] : 0;
    __syncthreads();
#pragma unroll
    for (int off = 1; off < 128; off <<= 1) {
        int x = 0;
        if (t < 128 && t >= off) x = sb[t - off];
        __syncthreads();
        if (t < 128) sb[t] += x;
        __syncthreads();
    }
    int i = blockIdx.x * 256 + t;
    if (i < NN) {
        int seg = i >> 10;
        int pre = (seg > 0) ? sb[seg - 1] : 0;
        int s = g_start[i] + pre;
        g_start[i] = s;
        g_csr[s] = i;          // self-loop entry at slot 0
    }
}

__global__ void scatter_kernel(const int* __restrict__ src,
                               const int* __restrict__ dst, int E) {
    int e = blockIdx.x * blockDim.x + threadIdx.x;
    if (e < E)
        g_csr[g_start[dst[e]] + g_rank[e]] = src[e];
}

// ---------------- tf32 mma.sync GEMM1 + fused alpha epilogue ----------------
#define KC 32
#define ASTRIDE 36

__global__ __launch_bounds__(256) void sgemm1_mma_kernel(const float* __restrict__ A,
                                                         const float* __restrict__ a_src,
                                                         const float* __restrict__ a_dst) {
    __shared__ uint32_t As[2][128 * ASTRIDE];
    __shared__ uint32_t Bs[2][64 * ASTRIDE];
    __shared__ float sattn[128];
    int t = threadIdx.x;
    int lane = t & 31, wid = t >> 5;
    int g = lane >> 2, tg = lane & 3;
    int warpM = (wid & 3) * 32;
    int warpN = (wid >> 2) * 32;
    int row0 = blockIdx.x * 128;

    if (t < 64) sattn[t] = a_src[t];
    else if (t < 128) sattn[t] = a_dst[t - 64];

    float c[2][4][4];
#pragma unroll
    for (int mi = 0; mi < 2; mi++)
#pragma unroll
        for (int ni = 0; ni < 4; ni++)
#pragma unroll
            for (int q = 0; q < 4; q++) c[mi][ni][q] = 0.f;

#pragma unroll
    for (int i = 0; i < 4; i++) {
        int idx = t + i * 256;
        int r = idx >> 3, q = idx & 7;
        int row = row0 + r;
        int rc = row < NN ? row : NN - 1;
        int sz = row < NN ? 16 : 0;
        cpa16(smem_u32(&As[0][r * ASTRIDE + q * 4]),
              A + (size_t)rc * 512 + q * 4, sz);
    }
#pragma unroll
    for (int i = 0; i < 2; i++) {
        int idx = t + i * 256;
        int r = idx >> 3, q = idx & 7;
        cpa16(smem_u32(&Bs[0][r * ASTRIDE + q * 4]),
              g_W1t + (size_t)r * 512 + q * 4, 16);
    }
    CPA_COMMIT();

    for (int cidx = 0; cidx < 16; cidx++) {
        int b = cidx & 1;
        if (cidx < 15) {
            int kk = (cidx + 1) * KC;
            int bn = b ^ 1;
#pragma unroll
            for (int i = 0; i < 4; i++) {
                int idx = t + i * 256;
                int r = idx >> 3, q = idx & 7;
                int row = row0 + r;
                int rc = row < NN ? row : NN - 1;
                int sz = row < NN ? 16 : 0;
                cpa16(smem_u32(&As[bn][r * ASTRIDE + q * 4]),
                      A + (size_t)rc * 512 + kk + q * 4, sz);
            }
#pragma unroll
            for (int i = 0; i < 2; i++) {
                int idx = t + i * 256;
                int r = idx >> 3, q = idx & 7;
                cpa16(smem_u32(&Bs[bn][r * ASTRIDE + q * 4]),
                      g_W1t + (size_t)r * 512 + kk + q * 4, 16);
            }
            CPA_COMMIT();
            CPA_WAIT(1);
        } else {
            CPA_WAIT(0);
        }
        __syncthreads();
#pragma unroll
        for (int k8 = 0; k8 < 4; k8++) {
            int kb = k8 * 8;
            uint32_t a[2][4], bb[4][2];
#pragma unroll
            for (int mi = 0; mi < 2; mi++) {
                int m = warpM + mi * 16;
                a[mi][0] = As[b][(m + g) * ASTRIDE + kb + tg];
                a[mi][1] = As[b][(m + g + 8) * ASTRIDE + kb + tg];
                a[mi][2] = As[b][(m + g) * ASTRIDE + kb + tg + 4];
                a[mi][3] = As[b][(m + g + 8) * ASTRIDE + kb + tg + 4];
            }
#pragma unroll
            for (int ni = 0; ni < 4; ni++) {
                int n = warpN + ni * 8;
                bb[ni][0] = Bs[b][(n + g) * ASTRIDE + kb + tg];
                bb[ni][1] = Bs[b][(n + g) * ASTRIDE + kb + tg + 4];
            }
#pragma unroll
            for (int mi = 0; mi < 2; mi++)
#pragma unroll
                for (int ni = 0; ni < 4; ni++)
                    mma_tf32(c[mi][ni][0], c[mi][ni][1], c[mi][ni][2], c[mi][ni][3],
                             a[mi][0], a[mi][1], a[mi][2], a[mi][3],
                             bb[ni][0], bb[ni][1]);
        }
        __syncthreads();
    }

    // ---- fused epilogue: stage bf16 tile in smem (reuse As[0]) ----
    uint32_t* Hs = &As[0][0];
#pragma unroll
    for (int mi = 0; mi < 2; mi++) {
        int r0 = warpM + mi * 16 + g;
        int r1 = r0 + 8;
#pragma unroll
        for (int ni = 0; ni < 4; ni++) {
            int cp = (warpN + ni * 8 + tg * 2) >> 1;   // col-pair index 0..31
            Hs[r0 * ASTRIDE + cp] =
                bf2_bits(__floats2bfloat162_rn(c[mi][ni][0], c[mi][ni][1]));
            Hs[r1 * ASTRIDE + cp] =
                bf2_bits(__floats2bfloat162_rn(c[mi][ni][2], c[mi][ni][3]));
        }
    }
    __syncthreads();
    // write h1b: thread t -> row t>>1, half t&1 (32B each)
    {
        int r = t >> 1, hf = t & 1;
        int row = row0 + r;
        if (row < NN) {
            const uint32_t* sp = &Hs[r * ASTRIDE + hf * 16];
            uint4* dp = reinterpret_cast<uint4*>(g_h1b + (size_t)row * 64 + hf * 32);
            dp[0] = *reinterpret_cast<const uint4*>(sp);
            dp[1] = *reinterpret_cast<const uint4*>(sp + 4);
            dp[2] = *reinterpret_cast<const uint4*>(sp + 8);
            dp[3] = *reinterpret_cast<const uint4*>(sp + 12);
        }
    }
    // alpha logits: threads 0-127 -> a_src dot; 128-255 -> a_dst dot
    {
        int r = t & 127;
        int row = row0 + r;
        if (row < NN) {
            const __nv_bfloat162* hp = reinterpret_cast<const __nv_bfloat162*>(&Hs[r * ASTRIDE]);
            const float* coef = sattn + (t < 128 ? 0 : 64);
            float res[8];
#pragma unroll
            for (int h = 0; h < 8; h++) {
                float s = 0.f;
#pragma unroll
                for (int q = 0; q < 4; q++) {
                    float2 f = __bfloat1622float2(hp[h * 4 + q]);
                    s += f.x * coef[h * 8 + 2 * q] + f.y * coef[h * 8 + 2 * q + 1];
                }
                res[h] = s;
            }
            float* dst = (t < 128 ? g_as1 : g_ad1) + (size_t)row * 8;
            *reinterpret_cast<float4*>(dst) = make_float4(res[0], res[1], res[2], res[3]);
            *reinterpret_cast<float4*>(dst + 4) = make_float4(res[4], res[5], res[6], res[7]);
        }
    }
}

// ---- layer-1 gather (8 lanes/node) + FUSED gemm2 + alpha2 epilogue --------
// layout identical to the proven R13 gather1; only the per-node tail changes.
__global__ __launch_bounds__(256) void gather1_kernel(const float* __restrict__ b1,
                                                      const float* __restrict__ W2,
                                                      const float* __restrict__ a_src2,
                                                      const float* __restrict__ a_dst2) {
    __shared__ float sW[448];
    __shared__ float sb1[64];
    __shared__ float sa2[8], sd2[8];
    {
        int t = threadIdx.x;
        for (int j = t; j < 448; j += 256) sW[j] = W2[j];
        if (t < 64) sb1[t] = b1[t];
        if (t < 7) sa2[t] = a_src2[t];
        if (t >= 32 && t < 39) sd2[t - 32] = a_dst2[t - 32];
    }
    __syncthreads();

    int gid = blockIdx.x * blockDim.x + threadIdx.x;
    int n = gid >> 3;
    if (n >= NN) return;
    int h = gid & 7;
    float ad_h = g_ad1[n * 8 + h];
    int st = g_start[n];
    int deg = g_cnt[n];                 // includes self
    float acc[8];
#pragma unroll
    for (int j = 0; j < 8; j++) acc[j] = 0.f;
    float den = 0.f;
    int i = 0;
    for (; i + 2 <= deg; i += 2) {
        int s0 = g_csr[st + i];
        int s1 = g_csr[st + i + 1];
        float w0 = lrexp(g_as1[s0 * 8 + h] + ad_h);
        float w1 = lrexp(g_as1[s1 * 8 + h] + ad_h);
        uint4 r0 = *reinterpret_cast<const uint4*>(g_h1b + (size_t)s0 * 64 + h * 8);
        uint4 r1 = *reinterpret_cast<const uint4*>(g_h1b + (size_t)s1 * 64 + h * 8);
        const __nv_bfloat162* f0 = reinterpret_cast<const __nv_bfloat162*>(&r0);
        const __nv_bfloat162* f1 = reinterpret_cast<const __nv_bfloat162*>(&r1);
#pragma unroll
        for (int q = 0; q < 4; q++) {
            float2 a0 = __bfloat1622float2(f0[q]);
            float2 a1 = __bfloat1622float2(f1[q]);
            acc[2 * q] += w0 * a0.x + w1 * a1.x;
            acc[2 * q + 1] += w0 * a0.y + w1 * a1.y;
        }
        den += w0 + w1;
    }
    if (i < deg) {
        int s0 = g_csr[st + i];
        float w0 = lrexp(g_as1[s0 * 8 + h] + ad_h);
        uint4 r0 = *reinterpret_cast<const uint4*>(g_h1b + (size_t)s0 * 64 + h * 8);
        const __nv_bfloat162* f0 = reinterpret_cast<const __nv_bfloat162*>(&r0);
#pragma unroll
        for (int q = 0; q < 4; q++) {
            float2 a0 = __bfloat1622float2(f0[q]);
            acc[2 * q] += w0 * a0.x;
            acc[2 * q + 1] += w0 * a0.y;
        }
        den += w0;
    }
    float inv = 1.0f / (den + 1e-16f);
    // finalize this head's 8 channels in-place
#pragma unroll
    for (int j = 0; j < 8; j++)
        acc[j] = acc[j] * inv + sb1[h * 8 + j];
    // fused gemm2: partial h2 from this lane's 8 channels
    float ph[7];
#pragma unroll
    for (int c = 0; c < 7; c++) ph[c] = 0.f;
#pragma unroll
    for (int j = 0; j < 8; j++) {
        float v = acc[j];
        const float* wr = &sW[(h * 8 + j) * 7];
#pragma unroll
        for (int c = 0; c < 7; c++) ph[c] += v * wr[c];
    }
    // 8-lane butterfly sum (lanes of one node are consecutive)
#pragma unroll
    for (int c = 0; c < 7; c++) {
        ph[c] += __shfl_xor_sync(0xffffffffu, ph[c], 1);
        ph[c] += __shfl_xor_sync(0xffffffffu, ph[c], 2);
        ph[c] += __shfl_xor_sync(0xffffffffu, ph[c], 4);
    }
    if (h == 0) {
        float s2 = 0.f, d2 = 0.f;
#pragma unroll
        for (int c = 0; c < 7; c++) {
            s2 += ph[c] * sa2[c];
            d2 += ph[c] * sd2[c];
        }
        uint4 pk;
        pk.x = bf2_bits(__floats2bfloat162_rn(ph[0], ph[1]));
        pk.y = bf2_bits(__floats2bfloat162_rn(ph[2], ph[3]));
        pk.z = bf2_bits(__floats2bfloat162_rn(ph[4], ph[5]));
        pk.w = bf2_bits(__floats2bfloat162_rn(ph[6], 1.0f));
        *reinterpret_cast<uint4*>(g_h2b + (size_t)n * 8) = pk;
        g_as2[n] = s2;
        g_ad2[n] = d2;
    }
}

// ---------------- layer-2 gather (8 lanes/node, bf16 h2, log_softmax) ------
__global__ __launch_bounds__(256) void gather2_kernel(const float* __restrict__ b2,
                                                      float* __restrict__ out) {
    int gid = blockIdx.x * blockDim.x + threadIdx.x;
    int n = gid >> 3;
    if (n >= NN) return;
    int c = gid & 7;
    float ad = g_ad2[n];
    int st = g_start[n];
    int deg = g_cnt[n];                 // includes self
    float acc = 0.f;
    int i = 0;
    for (; i + 2 <= deg; i += 2) {
        int s0 = g_csr[st + i];
        int s1 = g_csr[st + i + 1];
        float w0 = lrexp(g_as2[s0] + ad);
        float w1 = lrexp(g_as2[s1] + ad);
        acc += w0 * __bfloat162float(g_h2b[(size_t)s0 * 8 + c]) +
               w1 * __bfloat162float(g_h2b[(size_t)s1 * 8 + c]);
    }
    if (i < deg) {
        int s0 = g_csr[st + i];
        float w0 = lrexp(g_as2[s0] + ad);
        acc += w0 * __bfloat162float(g_h2b[(size_t)s0 * 8 + c]);
    }
    float den = __shfl_sync(0xffffffffu, acc, (threadIdx.x & ~7) | 7);
    float inv = 1.0f / (den + 1e-16f);
    float o = (c < 7) ? (acc * inv + b2[c]) : -1e30f;
    float m = o;
#pragma unroll
    for (int off = 1; off < 8; off <<= 1)
        m = fmaxf(m, __shfl_xor_sync(0xffffffffu, m, off));
    float ex = (c < 7) ? __expf(o - m) : 0.f;
    float sum = ex;
#pragma unroll
    for (int off = 1; off < 8; off <<= 1)
        sum += __shfl_xor_sync(0xffffffffu, sum, off);
    float lse = m + logf(sum);
    if (c < 7) out[(size_t)n * 7 + c] = o - lse;
}

// ---------------- launcher (sequential, single stream) ---------------------
extern "C" void kernel_launch(void* const* d_in, const int* in_sizes, int n_in,
                              void* d_out, int out_size) {
    const float* x    = (const float*)d_in[0];
    const int*   ei   = (const int*)d_in[1];
    const float* W1   = (const float*)d_in[2];
    const float* as1  = (const float*)d_in[3];
    const float* ad1  = (const float*)d_in[4];
    const float* b1   = (const float*)d_in[5];
    const float* W2   = (const float*)d_in[6];
    const float* as2  = (const float*)d_in[7];
    const float* ad2  = (const float*)d_in[8];
    const float* b2   = (const float*)d_in[9];
    float* out = (float*)d_out;
    int E = in_sizes[1] / 2;
    const int* src = ei;
    const int* dst = ei + E;

    prep_kernel<<<(NN + 255) / 256, 256>>>(W1);
    hist_kernel<<<(E + 255) / 256, 256>>>(dst, E);
    scan1_kernel<<<NBLK, 256>>>();
    scan3_kernel<<<(NN + 255) / 256, 256>>>();
    scatter_kernel<<<(E + 255) / 256, 256>>>(src, dst, E);

    sgemm1_mma_kernel<<<(NN + 127) / 128, 256>>>(x, as1, ad1);
    gather1_kernel<<<(NN * 8 + 255) / 256, 256>>>(b1, W2, as2, ad2);
    gather2_kernel<<<(NN * 8 + 255) / 256, 256>>>(b2, out);
}